// round 2
// baseline (speedup 1.0000x reference)
#include <cuda_runtime.h>

#define T_STEPS 16384
#define X_DIM   512
#define H_DIM   1024
#define NBLK    128
#define ROWS_PER_BLK (H_DIM / NBLK)    // 8 rows per block
#define NTHREADS (ROWS_PER_BLK * 32)   // 256 threads, 1 warp per row
#define RING    8                      // ring slots (skew bound is ~1 step)

// Tagged ring: word = (tag << 32) | fp32_bits, tag = step+1 (0 == empty).
// No memset needed: bss zero-init, and across graph replays a stale tag can
// only match the same step index -> identical (deterministic) value.
__device__ unsigned long long g_ring[RING][H_DIM];

__device__ __forceinline__ unsigned long long ld_relaxed_u64(const unsigned long long* p) {
    unsigned long long v;
    asm volatile("ld.relaxed.gpu.global.u64 %0, [%1];" : "=l"(v) : "l"(p) : "memory");
    return v;
}
__device__ __forceinline__ void st_relaxed_u64(unsigned long long* p, unsigned long long v) {
    asm volatile("st.relaxed.gpu.global.u64 [%0], %1;" :: "l"(p), "l"(v) : "memory");
}

__global__ void __launch_bounds__(NTHREADS, 1)
rnn_scan_kernel(const float* __restrict__ x_seq,
                const float* __restrict__ h0,
                const float* __restrict__ A_raw,
                const float* __restrict__ B,
                const float* __restrict__ c,
                float* __restrict__ out)
{
    const int warp = threadIdx.x >> 5;
    const int lane = threadIdx.x & 31;
    const int row  = blockIdx.x * ROWS_PER_BLK + warp;

    __shared__ float Bs[ROWS_PER_BLK][X_DIM];      // 16 KB
    __shared__ float h_sm[2][H_DIM];               // 8 KB double buffer

    // ---- Prologue: A = 0.9 I + 0.1 A_raw, row in registers.
    float a[32];
#pragma unroll
    for (int k = 0; k < 32; ++k) {
        int j = lane + 32 * k;
        float v = 0.1f * A_raw[(size_t)row * H_DIM + j];
        if (j == row) v += 0.9f;
        a[k] = v;
    }
    for (int i = threadIdx.x; i < ROWS_PER_BLK * X_DIM; i += NTHREADS) {
        int rr = i / X_DIM, jj = i % X_DIM;
        Bs[rr][jj] = B[((size_t)blockIdx.x * ROWS_PER_BLK + rr) * X_DIM + jj];
    }
    const float c_r = (lane == 0) ? c[row] : 0.0f;

    // Step 0 consumes h0: prefill buffer 0.
    for (int i = threadIdx.x; i < H_DIM; i += NTHREADS)
        h_sm[0][i] = h0[i];
    __syncthreads();

    for (int t = 0; t < T_STEPS; ++t) {
        const int cur = t & 1;

        // ---- 1) Input projection partial (fills otherwise-dead time).
        const float* xt = x_seq + (size_t)t * X_DIM;
        float xv[X_DIM / 32];
#pragma unroll
        for (int k = 0; k < X_DIM / 32; ++k) xv[k] = xt[lane + 32 * k];
        float b0 = 0.f, b1 = 0.f, b2 = 0.f, b3 = 0.f;
#pragma unroll
        for (int k = 0; k < X_DIM / 32; k += 4) {
            b0 += Bs[warp][lane + 32 * (k + 0)] * xv[k + 0];
            b1 += Bs[warp][lane + 32 * (k + 1)] * xv[k + 1];
            b2 += Bs[warp][lane + 32 * (k + 2)] * xv[k + 2];
            b3 += Bs[warp][lane + 32 * (k + 3)] * xv[k + 3];
        }
        float acc = ((b0 + b1) + (b2 + b3)) + c_r;

        // ---- 2) A . h_t from smem (bank-conflict-free: bank == lane).
        float hv[32];
#pragma unroll
        for (int k = 0; k < 32; ++k) hv[k] = h_sm[cur][lane + 32 * k];
        float s0 = 0.f, s1 = 0.f, s2 = 0.f, s3 = 0.f;
#pragma unroll
        for (int k = 0; k < 32; k += 4) {
            s0 += a[k + 0] * hv[k + 0];
            s1 += a[k + 1] * hv[k + 1];
            s2 += a[k + 2] * hv[k + 2];
            s3 += a[k + 3] * hv[k + 3];
        }
        acc += (s0 + s1) + (s2 + s3);

        // ---- 3) Warp reduce, tanh, publish tagged word + output row.
#pragma unroll
        for (int off = 16; off; off >>= 1)
            acc += __shfl_xor_sync(0xffffffffu, acc, off);

        if (lane == 0) {
            float hval = tanhf(acc);
            out[(size_t)t * H_DIM + row] = hval;
            unsigned long long w =
                ((unsigned long long)(unsigned)(t + 1) << 32) | __float_as_uint(hval);
            st_relaxed_u64(&g_ring[t & (RING - 1)][row], w);
        }

        // ---- 4) Cooperative gather of h_{t+1}... i.e. the h just produced
        // (tag t+1) into the other smem buffer. 4 coalesced words/thread,
        // retry only on misses. Tag and value travel in one atomic 64b word.
        if (t + 1 < T_STEPS) {
            const unsigned want = (unsigned)(t + 1);
            unsigned long long* slot = g_ring[t & (RING - 1)];
            unsigned long long q[4];
#pragma unroll
            for (int k = 0; k < 4; ++k)
                q[k] = ld_relaxed_u64(&slot[threadIdx.x + NTHREADS * k]);
            for (;;) {
                bool miss = false;
#pragma unroll
                for (int k = 0; k < 4; ++k) {
                    if ((unsigned)(q[k] >> 32) != want) {
                        q[k] = ld_relaxed_u64(&slot[threadIdx.x + NTHREADS * k]);
                        if ((unsigned)(q[k] >> 32) != want) miss = true;
                    }
                }
                if (!miss) break;
            }
#pragma unroll
            for (int k = 0; k < 4; ++k)
                h_sm[cur ^ 1][threadIdx.x + NTHREADS * k] = __uint_as_float((unsigned)q[k]);
        }
        __syncthreads();
    }
}

extern "C" void kernel_launch(void* const* d_in, const int* in_sizes, int n_in,
                              void* d_out, int out_size)
{
    const float* x_seq = (const float*)d_in[0];
    const float* h0    = (const float*)d_in[1];
    const float* A_raw = (const float*)d_in[2];
    const float* B     = (const float*)d_in[3];
    const float* c     = (const float*)d_in[4];
    float* out = (float*)d_out;

    rnn_scan_kernel<<<NBLK, NTHREADS>>>(x_seq, h0, A_raw, B, c, out);
}